// round 13
// baseline (speedup 1.0000x reference)
#include <cuda_runtime.h>
#include <cuda_bf16.h>
#include <math.h>
#include <stdint.h>

// ---------------- problem constants (fixed dataset) ----------------
#define MAX_N 20000
#define MAX_E 320000
#define NGRAPH 32

// ---------------- scratch (static device memory; no allocs) --------
__device__ float g_bufA[MAX_N * 1024];
__device__ float g_bufB[MAX_N * 1024];
__device__ float g_bufC[MAX_N * 1024];
__device__ float g_es[MAX_N * 4];
__device__ float g_ed[MAX_N * 4];
__device__ int   g_deg[MAX_N];
__device__ int   g_off[MAX_N + 1];
__device__ int   g_cur[MAX_N];
__device__ int   g_srcidx[MAX_E];
__device__ int   g_gcnt[NGRAPH];
__device__ int   g_goff[NGRAPH];
__device__ float g_pooled[NGRAPH * 768];
// bf16 hi/lo activation slots (double-rounded split), stride = feature dim
__device__ __nv_bfloat16 g_h0[MAX_N * 1024], g_l0[MAX_N * 1024];
__device__ __nv_bfloat16 g_h1[MAX_N * 1024], g_l1[MAX_N * 1024];
// bf16 hi/lo transposed weights, [N,K] K-major
__device__ __nv_bfloat16 g_wPh[768 * 768],   g_wPl[768 * 768];
__device__ __nv_bfloat16 g_w1h[1024 * 768],  g_w1l[1024 * 768];
__device__ __nv_bfloat16 g_w2h[1024 * 1024], g_w2l[1024 * 1024];
__device__ __nv_bfloat16 g_w3h[256 * 1024],  g_w3l[256 * 1024];

// ---------------- helpers ----------------
__device__ __forceinline__ float lrelu(float x) { return x > 0.f ? x : 0.2f * x; }
__device__ __forceinline__ float elu(float x)   { return x > 0.f ? x : expm1f(x); }

__device__ __forceinline__ void split_bf16(float x, __nv_bfloat16& h, __nv_bfloat16& l) {
    h = __float2bfloat16(x);
    l = __float2bfloat16(x - __bfloat162float(h));
}
__device__ __forceinline__ uint32_t smem_u32(const void* p) {
    uint32_t a;
    asm("{ .reg .u64 t; cvta.to.shared.u64 t, %1; cvt.u32.u64 %0, t; }" : "=r"(a) : "l"(p));
    return a;
}
__device__ __forceinline__ void cp_async16(uint32_t saddr, const void* gaddr, int srcsz) {
    asm volatile("cp.async.cg.shared.global [%0], [%1], 16, %2;"
                 :: "r"(saddr), "l"(gaddr), "r"(srcsz) : "memory");
}
__device__ __forceinline__ void mma_bf16(float* d, const uint32_t* a, const uint32_t* b) {
    asm volatile(
        "mma.sync.aligned.m16n8k16.row.col.f32.bf16.bf16.f32 "
        "{%0,%1,%2,%3}, {%4,%5,%6,%7}, {%8,%9}, {%0,%1,%2,%3};"
        : "+f"(d[0]), "+f"(d[1]), "+f"(d[2]), "+f"(d[3])
        : "r"(a[0]), "r"(a[1]), "r"(a[2]), "r"(a[3]), "r"(b[0]), "r"(b[1]));
}
__device__ __forceinline__ void ldm_x4(uint32_t* r, uint32_t addr) {
    asm volatile("ldmatrix.sync.aligned.m8n8.x4.shared.b16 {%0,%1,%2,%3}, [%4];"
                 : "=r"(r[0]), "=r"(r[1]), "=r"(r[2]), "=r"(r[3]) : "r"(addr));
}

// ---------------- bf16x3 mma.sync GEMM: C[M,N] = A @ Bt^T -------------------
// A given as bf16 hi/lo [M,K]; Bt as bf16 hi/lo [N,K] (weights pre-transposed).
// D = Ahi*Bhi + Ahi*Blo + Alo*Bhi  (fp32 accumulate) ~= fp32 GEMM, err ~2^-18.
// CTA tile 128(M) x 256(N), BK=32, 3-stage cp.async pipeline, 8 warps (2x4),
// warp tile 64x64. Fragments via ldmatrix.x4; rows padded to 80B -> the 8 rows
// of each ldmatrix phase start at banks {0,20,8,28,16,4,24,12}: conflict-free.
#define GEMM_BK 32
#define GEMM_STAGES 3
#define APAD 40                         // bf16 per row (32 data + 8 pad) = 80B
#define ROWB (APAD * 2)                 // 80 bytes
// byte offsets within a stage
#define OFF_AHI 0
#define OFF_ALO (128 * ROWB)            // 10240
#define OFF_BHI (2 * 128 * ROWB)        // 20480
#define OFF_BLO (OFF_BHI + 256 * ROWB)  // 40960
#define STG_BYTES (OFF_BLO + 256 * ROWB)    // 61440
#define GEMM_SMEM_TOTAL (GEMM_STAGES * STG_BYTES)

template<int ACT>   // 0 = none, 1 = ELU
__global__ void __launch_bounds__(256, 1)
mma_gemm(const __nv_bfloat16* __restrict__ Ahi, const __nv_bfloat16* __restrict__ Alo,
         const __nv_bfloat16* __restrict__ Bhi, const __nv_bfloat16* __restrict__ Blo,
         const float* __restrict__ bias, float* __restrict__ C,
         __nv_bfloat16* __restrict__ Chi, __nv_bfloat16* __restrict__ Clo,
         int M, int N, int K)
{
    extern __shared__ char smem_raw[];
    const int tid = threadIdx.x;
    const int lane = tid & 31;
    const int warp = tid >> 5;
    const int wm = warp & 1;         // 2 warps along M (64 rows each)
    const int wn = warp >> 1;        // 4 warps along N (64 cols each)
    const int row0 = blockIdx.y * 128;
    const int col0 = blockIdx.x * 256;
    const int qr = lane >> 2;        // groupID 0..7
    const int qc = lane & 3;         // threadID-in-group 0..3

    float acc[4][8][4];
#pragma unroll
    for (int i = 0; i < 4; i++)
#pragma unroll
        for (int j = 0; j < 8; j++)
#pragma unroll
            for (int r = 0; r < 4; r++) acc[i][j][r] = 0.f;

    const uint32_t sbase = smem_u32(smem_raw);
    const int NC = K / GEMM_BK;

    // per-lane ldmatrix row offsets (bytes, within a tile region)
    // A tile i: lanes 0-15 -> rows 0-15, lanes 16-31 -> same rows, +16B (k+8)
    const uint32_t aOff = (uint32_t)(wm * 64 + (lane & 15)) * ROWB + (lane >> 4) * 16;
    // B pair j2: r0/r1 = n rows 0-7 (k0 / k+8), r2/r3 = n rows 8-15
    const uint32_t bOff = (uint32_t)(wn * 64 + ((lane >> 4) << 3) + (lane & 7)) * ROWB
                          + ((lane >> 3) & 1) * 16;

    auto load_tile = [&](int c, int s) {
        const int k0 = c * GEMM_BK;
        const uint32_t stb = sbase + s * STG_BYTES;
#pragma unroll
        for (int t = 0; t < 12; t++) {          // 3072 16B chunks / 256 thr
            int id = t * 256 + tid;
            uint32_t soff;
            const __nv_bfloat16* g;
            int sz = 16;
            if (id < 1024) {                    // A hi | lo : 512 chunks each
                int half = id >> 9;             // 0 hi, 1 lo
                int wi = id & 511;
                int r = wi >> 2, q = wi & 3;
                soff = stb + (half ? OFF_ALO : OFF_AHI) + r * ROWB + q * 16;
                g = (half ? Alo : Ahi) + (size_t)(row0 + r) * K + k0 + q * 8;
                if (row0 + r >= M) sz = 0;
            } else {                            // B hi | lo : 1024 chunks each
                int id2 = id - 1024;
                int half = id2 >> 10;
                int wi = id2 & 1023;
                int r = wi >> 2, q = wi & 3;
                soff = stb + (half ? OFF_BLO : OFF_BHI) + r * ROWB + q * 16;
                g = (half ? Blo : Bhi) + (size_t)(col0 + r) * K + k0 + q * 8;
            }
            cp_async16(soff, g, sz);
        }
        asm volatile("cp.async.commit_group;" ::: "memory");
    };

    for (int c = 0; c < GEMM_STAGES && c < NC; c++) load_tile(c, c);

    for (int c = 0; c < NC; c++) {
        const int s = c % GEMM_STAGES;
        const int lag = NC - 1 - c;
        if (lag >= 2)      asm volatile("cp.async.wait_group 2;" ::: "memory");
        else if (lag == 1) asm volatile("cp.async.wait_group 1;" ::: "memory");
        else               asm volatile("cp.async.wait_group 0;" ::: "memory");
        __syncthreads();

        const uint32_t stb = sbase + s * STG_BYTES;

#pragma unroll
        for (int ks = 0; ks < 2; ks++) {
            const uint32_t kb = ks * 32;        // 16 bf16 = 32 bytes per k-step
            uint32_t ah[4][4], al[4][4], bh[8][2], bl[8][2];
#pragma unroll
            for (int i = 0; i < 4; i++) {
                ldm_x4(ah[i], stb + OFF_AHI + aOff + i * (16 * ROWB) + kb);
                ldm_x4(al[i], stb + OFF_ALO + aOff + i * (16 * ROWB) + kb);
            }
#pragma unroll
            for (int j2 = 0; j2 < 4; j2++) {
                uint32_t rh[4], rl[4];
                ldm_x4(rh, stb + OFF_BHI + bOff + j2 * (16 * ROWB) + kb);
                ldm_x4(rl, stb + OFF_BLO + bOff + j2 * (16 * ROWB) + kb);
                bh[2 * j2][0] = rh[0]; bh[2 * j2][1] = rh[1];
                bh[2 * j2 + 1][0] = rh[2]; bh[2 * j2 + 1][1] = rh[3];
                bl[2 * j2][0] = rl[0]; bl[2 * j2][1] = rl[1];
                bl[2 * j2 + 1][0] = rl[2]; bl[2 * j2 + 1][1] = rl[3];
            }
#pragma unroll
            for (int i = 0; i < 4; i++)
#pragma unroll
                for (int j = 0; j < 8; j++) {
                    mma_bf16(acc[i][j], ah[i], bh[j]);
                    mma_bf16(acc[i][j], ah[i], bl[j]);
                    mma_bf16(acc[i][j], al[i], bh[j]);
                }
        }
        __syncthreads();
        if (c + GEMM_STAGES < NC) load_tile(c + GEMM_STAGES, s);
    }

    // epilogue: d0,d1 = (row, 2qc..2qc+1); d2,d3 = (row+8, same cols)
#pragma unroll
    for (int i = 0; i < 4; i++) {
#pragma unroll
        for (int j = 0; j < 8; j++) {
            const int cc = col0 + wn * 64 + j * 8 + 2 * qc;
            float b0 = 0.f, b1 = 0.f;
            if (bias) { b0 = bias[cc]; b1 = bias[cc + 1]; }
#pragma unroll
            for (int half = 0; half < 2; half++) {
                int r = row0 + wm * 64 + i * 16 + qr + half * 8;
                if (r >= M) continue;
                float v0 = acc[i][j][half * 2 + 0] + b0;
                float v1 = acc[i][j][half * 2 + 1] + b1;
                if (ACT == 1) { v0 = elu(v0); v1 = elu(v1); }
                if (C) *(float2*)&C[(size_t)r * N + cc] = make_float2(v0, v1);
                if (Chi) {
                    __nv_bfloat16 h0, l0, h1, l1;
                    split_bf16(v0, h0, l0);
                    split_bf16(v1, h1, l1);
                    __nv_bfloat162 hp; hp.x = h0; hp.y = h1;
                    __nv_bfloat162 lp; lp.x = l0; lp.y = l1;
                    *(__nv_bfloat162*)&Chi[(size_t)r * N + cc] = hp;
                    *(__nv_bfloat162*)&Clo[(size_t)r * N + cc] = lp;
                }
            }
        }
    }
}

// ---------------- split fp32 -> bf16 hi/lo ----------------
__global__ void split_f32(const float* __restrict__ in,
                          __nv_bfloat16* __restrict__ hi, __nv_bfloat16* __restrict__ lo, int n)
{
    int i = blockIdx.x * blockDim.x + threadIdx.x;
    if (i < n) {
        __nv_bfloat16 h, l;
        split_bf16(in[i], h, l);
        hi[i] = h; lo[i] = l;
    }
}

// ---------------- weight transpose + split: out[N,K] = split(in[K,N]^T) ------
__global__ void transpose_split(const float* __restrict__ in,
                                __nv_bfloat16* __restrict__ oh, __nv_bfloat16* __restrict__ ol,
                                int K, int N)
{
    __shared__ float t[32][33];
    const int n0 = blockIdx.x * 32, k0 = blockIdx.y * 32;
    const int tx = threadIdx.x, ty = threadIdx.y;   // 32 x 8
#pragma unroll
    for (int i = 0; i < 32; i += 8)
        t[ty + i][tx] = in[(size_t)(k0 + ty + i) * N + n0 + tx];
    __syncthreads();
#pragma unroll
    for (int i = 0; i < 32; i += 8) {
        float v = t[tx][ty + i];
        __nv_bfloat16 h, l;
        split_bf16(v, h, l);
        oh[(size_t)(n0 + ty + i) * K + k0 + tx] = h;
        ol[(size_t)(n0 + ty + i) * K + k0 + tx] = l;
    }
}

// ---------------- attention score projections ----------------
template<int H>
__global__ void att_scores(const float* __restrict__ hW,
                           const float* __restrict__ a_src,
                           const float* __restrict__ a_dst,
                           int n)
{
    int warp = (blockIdx.x * blockDim.x + threadIdx.x) >> 5;
    int lane = threadIdx.x & 31;
    if (warp >= n * H) return;
    int node = warp / H, h = warp - node * H;
    const float* row = hW + (size_t)node * (H * 256) + h * 256;
    float ss = 0.f, sd = 0.f;
#pragma unroll
    for (int c = lane; c < 256; c += 32) {
        float v = row[c];
        ss = fmaf(v, a_src[h * 256 + c], ss);
        sd = fmaf(v, a_dst[h * 256 + c], sd);
    }
#pragma unroll
    for (int o = 16; o; o >>= 1) {
        ss += __shfl_xor_sync(0xFFFFFFFFu, ss, o);
        sd += __shfl_xor_sync(0xFFFFFFFFu, sd, o);
    }
    if (!lane) { g_es[node * H + h] = ss; g_ed[node * H + h] = sd; }
}

// ---------------- CSR construction ----------------
__global__ void zero_counts(int n) {
    int i = blockIdx.x * blockDim.x + threadIdx.x;
    if (i < n) g_deg[i] = 0;
    if (i < NGRAPH) g_gcnt[i] = 0;
}
__global__ void count_deg(const int* __restrict__ ei, int E) {
    int i = blockIdx.x * blockDim.x + threadIdx.x;
    if (i < E) atomicAdd(&g_deg[ei[E + i]], 1);
}
__global__ void count_graphs(const int* __restrict__ batch, int n) {
    int i = blockIdx.x * blockDim.x + threadIdx.x;
    if (i < n) atomicAdd(&g_gcnt[batch[i]], 1);
}
__global__ void scan_deg(int n) {
    __shared__ int part[1024];
    int tid = threadIdx.x;
    int per = (n + 1023) >> 10;
    int base = tid * per;
    int s = 0;
    for (int k = 0; k < per; k++) { int idx = base + k; if (idx < n) s += g_deg[idx]; }
    part[tid] = s;
    __syncthreads();
    for (int o = 1; o < 1024; o <<= 1) {
        int v = (tid >= o) ? part[tid - o] : 0;
        __syncthreads();
        part[tid] += v;
        __syncthreads();
    }
    int run = (tid == 0) ? 0 : part[tid - 1];
    for (int k = 0; k < per; k++) {
        int idx = base + k;
        if (idx < n) { g_off[idx] = run; g_cur[idx] = run; run += g_deg[idx]; }
    }
    if (tid == 0) g_off[n] = part[1023];
}
__global__ void graph_offsets() {
    if (threadIdx.x == 0) {
        int r = 0;
        for (int g = 0; g < NGRAPH; g++) { g_goff[g] = r; r += g_gcnt[g]; }
    }
}
__global__ void fill_csr(const int* __restrict__ ei, int E) {
    int i = blockIdx.x * blockDim.x + threadIdx.x;
    if (i < E) {
        int d = ei[E + i];
        int p = atomicAdd(&g_cur[d], 1);
        g_srcidx[p] = ei[i];
    }
}

// ---------------- fused GAT aggregation + bias + LayerNorm + ELU (+residual) ----
// Optionally emits bf16 hi/lo split of the output for the next GEMM.
template<int H, bool RES>
__global__ void gat_agg(const float* __restrict__ hW,
                        const float* __restrict__ bias,
                        const float* __restrict__ lng,
                        const float* __restrict__ lnb,
                        const float* __restrict__ resid,
                        float* __restrict__ out,
                        __nv_bfloat16* __restrict__ ohi,
                        __nv_bfloat16* __restrict__ olo)
{
    constexpr int CT = H * 256;
    constexpr int NT = CT / 4;
    const int i = blockIdx.x;
    const int tid = threadIdx.x;
    const int c0 = tid * 4;
    const int head = c0 >> 8;
    const int start = g_off[i], end = g_off[i + 1];

    float edv[H], selfl[H];
#pragma unroll
    for (int h = 0; h < H; h++) {
        edv[h] = g_ed[i * H + h];
        selfl[h] = lrelu(g_es[i * H + h] + edv[h]);
    }

    float mx[H];
#pragma unroll
    for (int h = 0; h < H; h++) mx[h] = selfl[h];
    for (int e = start + tid; e < end; e += NT) {
        int s = g_srcidx[e];
#pragma unroll
        for (int h = 0; h < H; h++) {
            float l = lrelu(g_es[s * H + h] + edv[h]);
            mx[h] = fmaxf(mx[h], l);
        }
    }
    __shared__ float red[NT];
#pragma unroll
    for (int h = 0; h < H; h++) {
        red[tid] = mx[h];
        __syncthreads();
        for (int o = NT / 2; o; o >>= 1) {
            if (tid < o) red[tid] = fmaxf(red[tid], red[tid + o]);
            __syncthreads();
        }
        mx[h] = red[0];
        __syncthreads();
    }

    float part[H];
#pragma unroll
    for (int h = 0; h < H; h++) part[h] = 0.f;
    for (int e = start + tid; e < end; e += NT) {
        int s = g_srcidx[e];
#pragma unroll
        for (int h = 0; h < H; h++) {
            float l = lrelu(g_es[s * H + h] + edv[h]);
            part[h] += __expf(l - mx[h]);
        }
    }
    float den[H];
#pragma unroll
    for (int h = 0; h < H; h++) {
        red[tid] = part[h];
        __syncthreads();
        for (int o = NT / 2; o; o >>= 1) {
            if (tid < o) red[tid] += red[tid + o];
            __syncthreads();
        }
        den[h] = red[0] + __expf(selfl[h] - mx[h]);
        __syncthreads();
    }

    const float m_h = mx[head];
    const float inv = 1.f / (den[head] + 1e-16f);
    const float edh = edv[head];
    float4 acc = make_float4(0.f, 0.f, 0.f, 0.f);
    for (int e = start; e < end; e++) {
        int s = g_srcidx[e];
        float l = lrelu(g_es[s * H + head] + edh);
        float a = __expf(l - m_h) * inv;
        float4 v = *(const float4*)&hW[(size_t)s * CT + c0];
        acc.x = fmaf(a, v.x, acc.x);
        acc.y = fmaf(a, v.y, acc.y);
        acc.z = fmaf(a, v.z, acc.z);
        acc.w = fmaf(a, v.w, acc.w);
    }
    {
        float a = __expf(selfl[head] - m_h) * inv;
        float4 v = *(const float4*)&hW[(size_t)i * CT + c0];
        acc.x = fmaf(a, v.x, acc.x);
        acc.y = fmaf(a, v.y, acc.y);
        acc.z = fmaf(a, v.z, acc.z);
        acc.w = fmaf(a, v.w, acc.w);
    }
    {
        float4 b = *(const float4*)&bias[c0];
        acc.x += b.x; acc.y += b.y; acc.z += b.z; acc.w += b.w;
    }

    float s1 = acc.x + acc.y + acc.z + acc.w;
    float s2 = acc.x * acc.x + acc.y * acc.y + acc.z * acc.z + acc.w * acc.w;
    red[tid] = s1; __syncthreads();
    for (int o = NT / 2; o; o >>= 1) { if (tid < o) red[tid] += red[tid + o]; __syncthreads(); }
    float S1 = red[0]; __syncthreads();
    red[tid] = s2; __syncthreads();
    for (int o = NT / 2; o; o >>= 1) { if (tid < o) red[tid] += red[tid + o]; __syncthreads(); }
    float S2 = red[0];

    float mu = S1 / (float)CT;
    float var = S2 / (float)CT - mu * mu;
    float rstd = rsqrtf(var + 1e-5f);
    float4 gv = *(const float4*)&lng[c0];
    float4 bv = *(const float4*)&lnb[c0];
    float o0 = elu((acc.x - mu) * rstd * gv.x + bv.x);
    float o1 = elu((acc.y - mu) * rstd * gv.y + bv.y);
    float o2 = elu((acc.z - mu) * rstd * gv.z + bv.z);
    float o3 = elu((acc.w - mu) * rstd * gv.w + bv.w);
    if (RES) {
        float4 rv = *(const float4*)&resid[(size_t)i * CT + c0];
        o0 += rv.x; o1 += rv.y; o2 += rv.z; o3 += rv.w;
    }
    *(float4*)&out[(size_t)i * CT + c0] = make_float4(o0, o1, o2, o3);

    if (ohi) {
        __nv_bfloat16 h[4], l[4];
        split_bf16(o0, h[0], l[0]);
        split_bf16(o1, h[1], l[1]);
        split_bf16(o2, h[2], l[2]);
        split_bf16(o3, h[3], l[3]);
        __nv_bfloat162 hp0; hp0.x = h[0]; hp0.y = h[1];
        __nv_bfloat162 hp1; hp1.x = h[2]; hp1.y = h[3];
        __nv_bfloat162 lp0; lp0.x = l[0]; lp0.y = l[1];
        __nv_bfloat162 lp1; lp1.x = l[2]; lp1.y = l[3];
        *(__nv_bfloat162*)&ohi[(size_t)i * CT + c0] = hp0;
        *(__nv_bfloat162*)&ohi[(size_t)i * CT + c0 + 2] = hp1;
        *(__nv_bfloat162*)&olo[(size_t)i * CT + c0] = lp0;
        *(__nv_bfloat162*)&olo[(size_t)i * CT + c0 + 2] = lp1;
    }
}

// ---------------- per-graph pooling: mean | max | sum ----------------
__global__ void pool_kernel(const float* __restrict__ x3) {
    int g = blockIdx.x;
    int tid = threadIdx.x;
    int s = g_goff[g], cnt = g_gcnt[g];
    float sum = 0.f, mx = -INFINITY;
    for (int k = 0; k < cnt; k++) {
        float v = x3[(size_t)(s + k) * 256 + tid];
        sum += v;
        mx = fmaxf(mx, v);
    }
    float mean = sum / fmaxf((float)cnt, 1.f);
    g_pooled[g * 768 + tid] = mean;
    g_pooled[g * 768 + 256 + tid] = mx;
    g_pooled[g * 768 + 512 + tid] = sum;
}

// ---------------- classifier head ----------------
__global__ void classify(const float* __restrict__ w1, const float* __restrict__ b1,
                         const float* __restrict__ w2, const float* __restrict__ b2,
                         float* __restrict__ outv)
{
    int g = blockIdx.x;
    int j = threadIdx.x;
    float s = b1[j];
    for (int k = 0; k < 768; k++)
        s = fmaf(g_pooled[g * 768 + k], w1[k * 128 + j], s);
    s = fmaxf(s, 0.f);
    float t = s * w2[j];
    __shared__ float red[128];
    red[j] = t; __syncthreads();
    for (int o = 64; o; o >>= 1) { if (j < o) red[j] += red[j + o]; __syncthreads(); }
    if (!j) outv[g] = red[0] + b2[0];
}

// ---------------- launch ----------------
extern "C" void kernel_launch(void* const* d_in, const int* in_sizes, int n_in,
                              void* d_out, int out_size)
{
    const float* x        = (const float*)d_in[0];
    const int*   ei       = (const int*)d_in[1];
    const int*   batch    = (const int*)d_in[2];
    const float* proj_w   = (const float*)d_in[3];
    const float* proj_b   = (const float*)d_in[4];
    const float* gat1_w   = (const float*)d_in[5];
    const float* att1_src = (const float*)d_in[6];
    const float* att1_dst = (const float*)d_in[7];
    const float* gat1_b   = (const float*)d_in[8];
    const float* ln1_g    = (const float*)d_in[9];
    const float* ln1_b    = (const float*)d_in[10];
    const float* gat2_w   = (const float*)d_in[11];
    const float* att2_src = (const float*)d_in[12];
    const float* att2_dst = (const float*)d_in[13];
    const float* gat2_b   = (const float*)d_in[14];
    const float* ln2_g    = (const float*)d_in[15];
    const float* ln2_b    = (const float*)d_in[16];
    const float* gat3_w   = (const float*)d_in[17];
    const float* att3_src = (const float*)d_in[18];
    const float* att3_dst = (const float*)d_in[19];
    const float* gat3_b   = (const float*)d_in[20];
    const float* ln3_g    = (const float*)d_in[21];
    const float* ln3_b    = (const float*)d_in[22];
    const float* cls1_w   = (const float*)d_in[23];
    const float* cls1_b   = (const float*)d_in[24];
    const float* cls2_w   = (const float*)d_in[25];
    const float* cls2_b   = (const float*)d_in[26];

    const int N = in_sizes[0] / 768;
    const int E = in_sizes[1] / 2;
    const int G = out_size;

    float* bufA; cudaGetSymbolAddress((void**)&bufA, g_bufA);
    float* bufB; cudaGetSymbolAddress((void**)&bufB, g_bufB);
    float* bufC; cudaGetSymbolAddress((void**)&bufC, g_bufC);
    __nv_bfloat16 *h0, *l0, *h1, *l1;
    cudaGetSymbolAddress((void**)&h0, g_h0); cudaGetSymbolAddress((void**)&l0, g_l0);
    cudaGetSymbolAddress((void**)&h1, g_h1); cudaGetSymbolAddress((void**)&l1, g_l1);
    __nv_bfloat16 *wPh, *wPl, *w1h, *w1l, *w2h, *w2l, *w3h, *w3l;
    cudaGetSymbolAddress((void**)&wPh, g_wPh); cudaGetSymbolAddress((void**)&wPl, g_wPl);
    cudaGetSymbolAddress((void**)&w1h, g_w1h); cudaGetSymbolAddress((void**)&w1l, g_w1l);
    cudaGetSymbolAddress((void**)&w2h, g_w2h); cudaGetSymbolAddress((void**)&w2l, g_w2l);
    cudaGetSymbolAddress((void**)&w3h, g_w3h); cudaGetSymbolAddress((void**)&w3l, g_w3l);

    cudaFuncSetAttribute(mma_gemm<0>, cudaFuncAttributeMaxDynamicSharedMemorySize, GEMM_SMEM_TOTAL);
    cudaFuncSetAttribute(mma_gemm<1>, cudaFuncAttributeMaxDynamicSharedMemorySize, GEMM_SMEM_TOTAL);

    // CSR + graph segmentation
    zero_counts<<<(N + 255) / 256, 256>>>(N);
    count_deg<<<(E + 255) / 256, 256>>>(ei, E);
    count_graphs<<<(N + 255) / 256, 256>>>(batch, N);
    scan_deg<<<1, 1024>>>(N);
    graph_offsets<<<1, 32>>>();
    fill_csr<<<(E + 255) / 256, 256>>>(ei, E);

    // operand preparation: split x, transpose+split weights
    split_f32<<<(N * 768 + 255) / 256, 256>>>(x, h1, l1, N * 768);
    dim3 tb(32, 8);
    transpose_split<<<dim3(768 / 32, 768 / 32), tb>>>(proj_w, wPh, wPl, 768, 768);
    transpose_split<<<dim3(1024 / 32, 768 / 32), tb>>>(gat1_w, w1h, w1l, 768, 1024);
    transpose_split<<<dim3(1024 / 32, 1024 / 32), tb>>>(gat2_w, w2h, w2l, 1024, 1024);
    transpose_split<<<dim3(256 / 32, 1024 / 32), tb>>>(gat3_w, w3h, w3l, 1024, 256);

    const int MT = (N + 127) / 128;

    // proj: h = elu(x @ proj_w + b) -> hi/lo slot0 only (feeds gemm1)
    mma_gemm<1><<<dim3(768 / 256, MT), 256, GEMM_SMEM_TOTAL>>>(
        h1, l1, wPh, wPl, proj_b, nullptr, h0, l0, N, 768, 768);

    // ---- GAT layer 1 ----
    mma_gemm<0><<<dim3(1024 / 256, MT), 256, GEMM_SMEM_TOTAL>>>(
        h0, l0, w1h, w1l, nullptr, bufB, nullptr, nullptr, N, 1024, 768);
    att_scores<4><<<(N * 4 + 7) / 8, 256>>>(bufB, att1_src, att1_dst, N);
    gat_agg<4, false><<<N, 256>>>(bufB, gat1_b, ln1_g, ln1_b, nullptr, bufC, h1, l1);   // bufC = x1

    // ---- GAT layer 2 ----
    mma_gemm<0><<<dim3(1024 / 256, MT), 256, GEMM_SMEM_TOTAL>>>(
        h1, l1, w2h, w2l, nullptr, bufB, nullptr, nullptr, N, 1024, 1024);
    att_scores<4><<<(N * 4 + 7) / 8, 256>>>(bufB, att2_src, att2_dst, N);
    gat_agg<4, true><<<N, 256>>>(bufB, gat2_b, ln2_g, ln2_b, bufC, bufA, h0, l0);       // x2 -> slot0

    // ---- GAT layer 3 ----
    mma_gemm<0><<<dim3(256 / 256, MT), 256, GEMM_SMEM_TOTAL>>>(
        h0, l0, w3h, w3l, nullptr, bufB, nullptr, nullptr, N, 256, 1024);
    att_scores<1><<<(N + 7) / 8, 256>>>(bufB, att3_src, att3_dst, N);
    gat_agg<1, false><<<N, 64>>>(bufB, gat3_b, ln3_g, ln3_b, nullptr, bufC, nullptr, nullptr); // x3

    // ---- pooling + classifier ----
    pool_kernel<<<G, 256>>>(bufC);
    classify<<<G, 128>>>(cls1_w, cls1_b, cls2_w, cls2_b, (float*)d_out);
}

// round 14
// speedup vs baseline: 1.1028x; 1.1028x over previous
#include <cuda_runtime.h>
#include <cuda_bf16.h>
#include <math.h>
#include <stdint.h>

// ---------------- problem constants (fixed dataset) ----------------
#define MAX_N 20000
#define MAX_E 320000
#define NGRAPH 32

// ---------------- scratch (static device memory; no allocs) --------
__device__ float g_bufA[MAX_N * 1024];
__device__ float g_bufB[MAX_N * 1024];
__device__ float g_bufC[MAX_N * 1024];
__device__ float g_es[MAX_N * 4];
__device__ float g_ed[MAX_N * 4];
__device__ int   g_deg[MAX_N];
__device__ int   g_off[MAX_N + 1];
__device__ int   g_cur[MAX_N];
__device__ int   g_srcidx[MAX_E];
__device__ int   g_gcnt[NGRAPH];
__device__ int   g_goff[NGRAPH];
__device__ float g_pooled[NGRAPH * 768];
// bf16 hi/lo activation slots (double-rounded split), stride = feature dim
__device__ __nv_bfloat16 g_h0[MAX_N * 1024], g_l0[MAX_N * 1024];
__device__ __nv_bfloat16 g_h1[MAX_N * 1024], g_l1[MAX_N * 1024];
// bf16 hi/lo transposed weights, [N,K] K-major
__device__ __nv_bfloat16 g_wPh[768 * 768],   g_wPl[768 * 768];
__device__ __nv_bfloat16 g_w1h[1024 * 768],  g_w1l[1024 * 768];
__device__ __nv_bfloat16 g_w2h[1024 * 1024], g_w2l[1024 * 1024];
__device__ __nv_bfloat16 g_w3h[256 * 1024],  g_w3l[256 * 1024];

// ---------------- helpers ----------------
__device__ __forceinline__ float lrelu(float x) { return x > 0.f ? x : 0.2f * x; }
__device__ __forceinline__ float elu(float x)   { return x > 0.f ? x : expm1f(x); }

__device__ __forceinline__ void split_bf16(float x, __nv_bfloat16& h, __nv_bfloat16& l) {
    h = __float2bfloat16(x);
    l = __float2bfloat16(x - __bfloat162float(h));
}
__device__ __forceinline__ uint32_t smem_u32(const void* p) {
    uint32_t a;
    asm("{ .reg .u64 t; cvta.to.shared.u64 t, %1; cvt.u32.u64 %0, t; }" : "=r"(a) : "l"(p));
    return a;
}
__device__ __forceinline__ void cp_async16(uint32_t saddr, const void* gaddr, int srcsz) {
    asm volatile("cp.async.cg.shared.global [%0], [%1], 16, %2;"
                 :: "r"(saddr), "l"(gaddr), "r"(srcsz) : "memory");
}
__device__ __forceinline__ void mma_bf16(float* d, const uint32_t* a, const uint32_t* b) {
    asm volatile(
        "mma.sync.aligned.m16n8k16.row.col.f32.bf16.bf16.f32 "
        "{%0,%1,%2,%3}, {%4,%5,%6,%7}, {%8,%9}, {%0,%1,%2,%3};"
        : "+f"(d[0]), "+f"(d[1]), "+f"(d[2]), "+f"(d[3])
        : "r"(a[0]), "r"(a[1]), "r"(a[2]), "r"(a[3]), "r"(b[0]), "r"(b[1]));
}
__device__ __forceinline__ void ldm_x4(uint32_t* r, uint32_t addr) {
    asm volatile("ldmatrix.sync.aligned.m8n8.x4.shared.b16 {%0,%1,%2,%3}, [%4];"
                 : "=r"(r[0]), "=r"(r[1]), "=r"(r[2]), "=r"(r[3]) : "r"(addr));
}

// ---------------- bf16x3 mma.sync GEMM: C[M,N] = A @ Bt^T -------------------
// A given as bf16 hi/lo [M,K]; Bt as bf16 hi/lo [N,K] (weights pre-transposed).
// D = Ahi*Bhi + Ahi*Blo + Alo*Bhi  (fp32 accumulate) ~= fp32 GEMM, err ~2^-18.
// CTA tile 128(M) x 128(N), BK=32, 2-stage cp.async double-buffer, 8 warps
// (2x4), warp tile 64x32, 2 CTAs/SM to fill sync/epilogue bubbles.
// Fragments via ldmatrix.x4; rows padded to 80B -> conflict-free phases.
#define GEMM_BK 32
#define GEMM_STAGES 2
#define APAD 40                         // bf16 per row (32 data + 8 pad) = 80B
#define ROWB (APAD * 2)                 // 80 bytes
#define TILEB (128 * ROWB)              // 10240 bytes per (matrix x hi/lo) tile
#define STG_BYTES (4 * TILEB)           // Ahi, Alo, Bhi, Blo = 40960
#define GEMM_SMEM_TOTAL (GEMM_STAGES * STG_BYTES)

template<int ACT>   // 0 = none, 1 = ELU
__global__ void __launch_bounds__(256, 2)
mma_gemm(const __nv_bfloat16* __restrict__ Ahi, const __nv_bfloat16* __restrict__ Alo,
         const __nv_bfloat16* __restrict__ Bhi, const __nv_bfloat16* __restrict__ Blo,
         const float* __restrict__ bias, float* __restrict__ C,
         __nv_bfloat16* __restrict__ Chi, __nv_bfloat16* __restrict__ Clo,
         int M, int N, int K)
{
    extern __shared__ char smem_raw[];
    const int tid = threadIdx.x;
    const int lane = tid & 31;
    const int warp = tid >> 5;
    const int wm = warp & 1;         // 2 warps along M (64 rows each)
    const int wn = warp >> 1;        // 4 warps along N (32 cols each)
    const int row0 = blockIdx.y * 128;
    const int col0 = blockIdx.x * 128;
    const int qr = lane >> 2;        // groupID 0..7
    const int qc = lane & 3;         // threadID-in-group 0..3

    float acc[4][4][4];
#pragma unroll
    for (int i = 0; i < 4; i++)
#pragma unroll
        for (int j = 0; j < 4; j++)
#pragma unroll
            for (int r = 0; r < 4; r++) acc[i][j][r] = 0.f;

    const uint32_t sbase = smem_u32(smem_raw);
    const int NC = K / GEMM_BK;

    // ldmatrix per-lane offsets (verified mapping from R12):
    // A: lanes 0-15 -> rows 0-15 @k0, lanes 16-31 -> rows 0-15 @k+8 (16B)
    const uint32_t aOff = (uint32_t)(wm * 64 + (lane & 15)) * ROWB + (lane >> 4) * 16;
    // B: lanes {0-7,8-15,16-23,24-31} -> {n0-7 k0, n0-7 k8, n8-15 k0, n8-15 k8}
    const uint32_t bOff = (uint32_t)(wn * 32 + ((lane >> 4) << 3) + (lane & 7)) * ROWB
                          + ((lane >> 3) & 1) * 16;

    auto load_tile = [&](int c, int s) {
        const int k0 = c * GEMM_BK;
        const uint32_t stb = sbase + s * STG_BYTES;
#pragma unroll
        for (int t = 0; t < 8; t++) {           // 2048 16B chunks / 256 thr
            int id = t * 256 + tid;
            int tile = id >> 9;                 // 0 Ahi, 1 Alo, 2 Bhi, 3 Blo
            int wi = id & 511;
            int r = wi >> 2, q = wi & 3;
            uint32_t soff = stb + tile * TILEB + r * ROWB + q * 16;
            const __nv_bfloat16* g;
            int sz = 16;
            if (tile == 0)      { g = Ahi + (size_t)(row0 + r) * K + k0 + q * 8; if (row0 + r >= M) sz = 0; }
            else if (tile == 1) { g = Alo + (size_t)(row0 + r) * K + k0 + q * 8; if (row0 + r >= M) sz = 0; }
            else if (tile == 2) { g = Bhi + (size_t)(col0 + r) * K + k0 + q * 8; }
            else                { g = Blo + (size_t)(col0 + r) * K + k0 + q * 8; }
            cp_async16(soff, g, sz);
        }
        asm volatile("cp.async.commit_group;" ::: "memory");
    };

    load_tile(0, 0);
    if (NC > 1) load_tile(1, 1);

    for (int c = 0; c < NC; c++) {
        const int s = c & 1;
        if (c < NC - 1) asm volatile("cp.async.wait_group 1;" ::: "memory");
        else            asm volatile("cp.async.wait_group 0;" ::: "memory");
        __syncthreads();

        const uint32_t stb = sbase + s * STG_BYTES;

#pragma unroll
        for (int ks = 0; ks < 2; ks++) {
            const uint32_t kb = ks * 32;        // 16 bf16 = 32 bytes per k-step
            uint32_t ah[4][4], al[4][4], bh[4][2], bl[4][2];
#pragma unroll
            for (int i = 0; i < 4; i++) {
                ldm_x4(ah[i], stb + 0 * TILEB + aOff + i * (16 * ROWB) + kb);
                ldm_x4(al[i], stb + 1 * TILEB + aOff + i * (16 * ROWB) + kb);
            }
#pragma unroll
            for (int j2 = 0; j2 < 2; j2++) {
                uint32_t rh[4], rl[4];
                ldm_x4(rh, stb + 2 * TILEB + bOff + j2 * (16 * ROWB) + kb);
                ldm_x4(rl, stb + 3 * TILEB + bOff + j2 * (16 * ROWB) + kb);
                bh[2 * j2][0] = rh[0]; bh[2 * j2][1] = rh[1];
                bh[2 * j2 + 1][0] = rh[2]; bh[2 * j2 + 1][1] = rh[3];
                bl[2 * j2][0] = rl[0]; bl[2 * j2][1] = rl[1];
                bl[2 * j2 + 1][0] = rl[2]; bl[2 * j2 + 1][1] = rl[3];
            }
#pragma unroll
            for (int i = 0; i < 4; i++)
#pragma unroll
                for (int j = 0; j < 4; j++) {
                    mma_bf16(acc[i][j], ah[i], bh[j]);
                    mma_bf16(acc[i][j], ah[i], bl[j]);
                    mma_bf16(acc[i][j], al[i], bh[j]);
                }
        }
        __syncthreads();
        if (c + 2 < NC) load_tile(c + 2, s);
    }

    // epilogue: d0,d1 = (row, 2qc..2qc+1); d2,d3 = (row+8, same cols)
#pragma unroll
    for (int i = 0; i < 4; i++) {
#pragma unroll
        for (int j = 0; j < 4; j++) {
            const int cc = col0 + wn * 32 + j * 8 + 2 * qc;
            float b0 = 0.f, b1 = 0.f;
            if (bias) { b0 = bias[cc]; b1 = bias[cc + 1]; }
#pragma unroll
            for (int half = 0; half < 2; half++) {
                int r = row0 + wm * 64 + i * 16 + qr + half * 8;
                if (r >= M) continue;
                float v0 = acc[i][j][half * 2 + 0] + b0;
                float v1 = acc[i][j][half * 2 + 1] + b1;
                if (ACT == 1) { v0 = elu(v0); v1 = elu(v1); }
                if (C) *(float2*)&C[(size_t)r * N + cc] = make_float2(v0, v1);
                if (Chi) {
                    __nv_bfloat16 h0, l0, h1, l1;
                    split_bf16(v0, h0, l0);
                    split_bf16(v1, h1, l1);
                    __nv_bfloat162 hp; hp.x = h0; hp.y = h1;
                    __nv_bfloat162 lp; lp.x = l0; lp.y = l1;
                    *(__nv_bfloat162*)&Chi[(size_t)r * N + cc] = hp;
                    *(__nv_bfloat162*)&Clo[(size_t)r * N + cc] = lp;
                }
            }
        }
    }
}

// ---------------- split fp32 -> bf16 hi/lo ----------------
__global__ void split_f32(const float* __restrict__ in,
                          __nv_bfloat16* __restrict__ hi, __nv_bfloat16* __restrict__ lo, int n)
{
    int i = blockIdx.x * blockDim.x + threadIdx.x;
    if (i < n) {
        __nv_bfloat16 h, l;
        split_bf16(in[i], h, l);
        hi[i] = h; lo[i] = l;
    }
}

// ---------------- weight transpose + split: out[N,K] = split(in[K,N]^T) ------
__global__ void transpose_split(const float* __restrict__ in,
                                __nv_bfloat16* __restrict__ oh, __nv_bfloat16* __restrict__ ol,
                                int K, int N)
{
    __shared__ float t[32][33];
    const int n0 = blockIdx.x * 32, k0 = blockIdx.y * 32;
    const int tx = threadIdx.x, ty = threadIdx.y;   // 32 x 8
#pragma unroll
    for (int i = 0; i < 32; i += 8)
        t[ty + i][tx] = in[(size_t)(k0 + ty + i) * N + n0 + tx];
    __syncthreads();
#pragma unroll
    for (int i = 0; i < 32; i += 8) {
        float v = t[tx][ty + i];
        __nv_bfloat16 h, l;
        split_bf16(v, h, l);
        oh[(size_t)(n0 + ty + i) * K + k0 + tx] = h;
        ol[(size_t)(n0 + ty + i) * K + k0 + tx] = l;
    }
}

// ---------------- attention score projections ----------------
template<int H>
__global__ void att_scores(const float* __restrict__ hW,
                           const float* __restrict__ a_src,
                           const float* __restrict__ a_dst,
                           int n)
{
    int warp = (blockIdx.x * blockDim.x + threadIdx.x) >> 5;
    int lane = threadIdx.x & 31;
    if (warp >= n * H) return;
    int node = warp / H, h = warp - node * H;
    const float* row = hW + (size_t)node * (H * 256) + h * 256;
    float ss = 0.f, sd = 0.f;
#pragma unroll
    for (int c = lane; c < 256; c += 32) {
        float v = row[c];
        ss = fmaf(v, a_src[h * 256 + c], ss);
        sd = fmaf(v, a_dst[h * 256 + c], sd);
    }
#pragma unroll
    for (int o = 16; o; o >>= 1) {
        ss += __shfl_xor_sync(0xFFFFFFFFu, ss, o);
        sd += __shfl_xor_sync(0xFFFFFFFFu, sd, o);
    }
    if (!lane) { g_es[node * H + h] = ss; g_ed[node * H + h] = sd; }
}

// ---------------- CSR construction ----------------
__global__ void zero_counts(int n) {
    int i = blockIdx.x * blockDim.x + threadIdx.x;
    if (i < n) g_deg[i] = 0;
    if (i < NGRAPH) g_gcnt[i] = 0;
}
__global__ void count_deg(const int* __restrict__ ei, int E) {
    int i = blockIdx.x * blockDim.x + threadIdx.x;
    if (i < E) atomicAdd(&g_deg[ei[E + i]], 1);
}
__global__ void count_graphs(const int* __restrict__ batch, int n) {
    int i = blockIdx.x * blockDim.x + threadIdx.x;
    if (i < n) atomicAdd(&g_gcnt[batch[i]], 1);
}
__global__ void scan_deg(int n) {
    __shared__ int part[1024];
    int tid = threadIdx.x;
    int per = (n + 1023) >> 10;
    int base = tid * per;
    int s = 0;
    for (int k = 0; k < per; k++) { int idx = base + k; if (idx < n) s += g_deg[idx]; }
    part[tid] = s;
    __syncthreads();
    for (int o = 1; o < 1024; o <<= 1) {
        int v = (tid >= o) ? part[tid - o] : 0;
        __syncthreads();
        part[tid] += v;
        __syncthreads();
    }
    int run = (tid == 0) ? 0 : part[tid - 1];
    for (int k = 0; k < per; k++) {
        int idx = base + k;
        if (idx < n) { g_off[idx] = run; g_cur[idx] = run; run += g_deg[idx]; }
    }
    if (tid == 0) g_off[n] = part[1023];
}
__global__ void graph_offsets() {
    if (threadIdx.x == 0) {
        int r = 0;
        for (int g = 0; g < NGRAPH; g++) { g_goff[g] = r; r += g_gcnt[g]; }
    }
}
__global__ void fill_csr(const int* __restrict__ ei, int E) {
    int i = blockIdx.x * blockDim.x + threadIdx.x;
    if (i < E) {
        int d = ei[E + i];
        int p = atomicAdd(&g_cur[d], 1);
        g_srcidx[p] = ei[i];
    }
}

// ---------------- fused GAT aggregation + bias + LayerNorm + ELU (+residual) ----
// Online-softmax single logit pass; shuffle reductions (~5 barriers/CTA);
// alpha precomputed per edge into smem (no redundant exp per thread).
template<int H, bool RES>
__global__ void gat_agg(const float* __restrict__ hW,
                        const float* __restrict__ bias,
                        const float* __restrict__ lng,
                        const float* __restrict__ lnb,
                        const float* __restrict__ resid,
                        float* __restrict__ out,
                        __nv_bfloat16* __restrict__ ohi,
                        __nv_bfloat16* __restrict__ olo)
{
    constexpr int CT = H * 256;
    constexpr int NT = CT / 4;
    constexpr int NW = NT / 32;
    constexpr int CHUNK = 64;

    __shared__ float2 wred[NW][H];
    __shared__ float  alpha_sm[CHUNK * H];
    __shared__ int    sidx_sm[CHUNK];
    __shared__ float  lnr[NW][2];

    const int i = blockIdx.x;
    const int tid = threadIdx.x;
    const int lane = tid & 31, wid = tid >> 5;
    const int c0 = tid * 4;
    const int head = c0 >> 8;
    const int start = g_off[i], end = g_off[i + 1];

    float edv[H], selfl[H];
#pragma unroll
    for (int h = 0; h < H; h++) {
        edv[h] = g_ed[i * H + h];
        selfl[h] = lrelu(g_es[i * H + h] + edv[h]);
    }

    // single online-softmax pass over edges (all heads)
    float m[H], s[H];
#pragma unroll
    for (int h = 0; h < H; h++) { m[h] = -1e30f; s[h] = 0.f; }
    for (int e = start + tid; e < end; e += NT) {
        int sd = g_srcidx[e];
#pragma unroll
        for (int h = 0; h < H; h++) {
            float l = lrelu(g_es[sd * H + h] + edv[h]);
            if (l > m[h]) { s[h] = s[h] * __expf(m[h] - l) + 1.f; m[h] = l; }
            else          { s[h] += __expf(l - m[h]); }
        }
    }
    // warp combine
#pragma unroll
    for (int off = 16; off; off >>= 1) {
#pragma unroll
        for (int h = 0; h < H; h++) {
            float m2 = __shfl_xor_sync(0xFFFFFFFFu, m[h], off);
            float s2 = __shfl_xor_sync(0xFFFFFFFFu, s[h], off);
            if (m2 > m[h]) { s[h] = s[h] * __expf(m[h] - m2) + s2; m[h] = m2; }
            else           { s[h] += s2 * __expf(m2 - m[h]); }
        }
    }
    if (lane == 0) {
#pragma unroll
        for (int h = 0; h < H; h++) wred[wid][h] = make_float2(m[h], s[h]);
    }
    __syncthreads();

    float M[H], inv[H];
#pragma unroll
    for (int h = 0; h < H; h++) {
        float Mv = -1e30f, Sv = 0.f;
#pragma unroll
        for (int w = 0; w < NW; w++) {
            float2 p = wred[w][h];
            if (p.x > Mv) { Sv = Sv * __expf(Mv - p.x) + p.y; Mv = p.x; }
            else          { Sv += p.y * __expf(p.x - Mv); }
        }
        // self-loop
        if (selfl[h] > Mv) { Sv = Sv * __expf(Mv - selfl[h]) + 1.f; Mv = selfl[h]; }
        else               { Sv += __expf(selfl[h] - Mv); }
        M[h] = Mv; inv[h] = 1.f / (Sv + 1e-16f);
    }

    // weighted gather (chunked, alpha precomputed)
    float4 acc;
    {
        float a = __expf(selfl[head] - M[head]) * inv[head];
        float4 v = *(const float4*)&hW[(size_t)i * CT + c0];
        acc = make_float4(a * v.x, a * v.y, a * v.z, a * v.w);
    }
    for (int base = start; base < end; base += CHUNK) {
        int nE = min(CHUNK, end - base);
        __syncthreads();    // protect alpha_sm/sidx_sm reuse
        int e2, hh;
        if (H == 4) { e2 = tid >> 2; hh = tid & 3; }
        else        { e2 = tid;      hh = 0; }
        if (e2 < nE) {
            int sd = g_srcidx[base + e2];
            if (hh == 0) sidx_sm[e2] = sd;
            float l = lrelu(g_es[sd * H + hh] + edv[hh]);
            alpha_sm[e2 * H + hh] = __expf(l - M[hh]) * inv[hh];
        }
        __syncthreads();
        for (int k = 0; k < nE; k++) {
            int sd = sidx_sm[k];
            float a = alpha_sm[k * H + head];
            float4 v = *(const float4*)&hW[(size_t)sd * CT + c0];
            acc.x = fmaf(a, v.x, acc.x);
            acc.y = fmaf(a, v.y, acc.y);
            acc.z = fmaf(a, v.z, acc.z);
            acc.w = fmaf(a, v.w, acc.w);
        }
    }
    {
        float4 b = *(const float4*)&bias[c0];
        acc.x += b.x; acc.y += b.y; acc.z += b.z; acc.w += b.w;
    }

    // LayerNorm via shuffle + one smem round
    float s1 = acc.x + acc.y + acc.z + acc.w;
    float s2 = acc.x * acc.x + acc.y * acc.y + acc.z * acc.z + acc.w * acc.w;
#pragma unroll
    for (int off = 16; off; off >>= 1) {
        s1 += __shfl_xor_sync(0xFFFFFFFFu, s1, off);
        s2 += __shfl_xor_sync(0xFFFFFFFFu, s2, off);
    }
    if (lane == 0) { lnr[wid][0] = s1; lnr[wid][1] = s2; }
    __syncthreads();
    float S1 = 0.f, S2 = 0.f;
#pragma unroll
    for (int w = 0; w < NW; w++) { S1 += lnr[w][0]; S2 += lnr[w][1]; }

    float mu = S1 / (float)CT;
    float var = S2 / (float)CT - mu * mu;
    float rstd = rsqrtf(var + 1e-5f);
    float4 gv = *(const float4*)&lng[c0];
    float4 bv = *(const float4*)&lnb[c0];
    float o0 = elu((acc.x - mu) * rstd * gv.x + bv.x);
    float o1 = elu((acc.y - mu) * rstd * gv.y + bv.y);
    float o2 = elu((acc.z - mu) * rstd * gv.z + bv.z);
    float o3 = elu((acc.w - mu) * rstd * gv.w + bv.w);
    if (RES) {
        float4 rv = *(const float4*)&resid[(size_t)i * CT + c0];
        o0 += rv.x; o1 += rv.y; o2 += rv.z; o3 += rv.w;
    }
    *(float4*)&out[(size_t)i * CT + c0] = make_float4(o0, o1, o2, o3);

    if (ohi) {
        __nv_bfloat16 h[4], l[4];
        split_bf16(o0, h[0], l[0]);
        split_bf16(o1, h[1], l[1]);
        split_bf16(o2, h[2], l[2]);
        split_bf16(o3, h[3], l[3]);
        __nv_bfloat162 hp0; hp0.x = h[0]; hp0.y = h[1];
        __nv_bfloat162 hp1; hp1.x = h[2]; hp1.y = h[3];
        __nv_bfloat162 lp0; lp0.x = l[0]; lp0.y = l[1];
        __nv_bfloat162 lp1; lp1.x = l[2]; lp1.y = l[3];
        *(__nv_bfloat162*)&ohi[(size_t)i * CT + c0] = hp0;
        *(__nv_bfloat162*)&ohi[(size_t)i * CT + c0 + 2] = hp1;
        *(__nv_bfloat162*)&olo[(size_t)i * CT + c0] = lp0;
        *(__nv_bfloat162*)&olo[(size_t)i * CT + c0 + 2] = lp1;
    }
}

// ---------------- per-graph pooling: mean | max | sum ----------------
__global__ void pool_kernel(const float* __restrict__ x3) {
    int g = blockIdx.x;
    int tid = threadIdx.x;
    int s = g_goff[g], cnt = g_gcnt[g];
    float sum = 0.f, mx = -INFINITY;
    for (int k = 0; k < cnt; k++) {
        float v = x3[(size_t)(s + k) * 256 + tid];
        sum += v;
        mx = fmaxf(mx, v);
    }
    float mean = sum / fmaxf((float)cnt, 1.f);
    g_pooled[g * 768 + tid] = mean;
    g_pooled[g * 768 + 256 + tid] = mx;
    g_pooled[g * 768 + 512 + tid] = sum;
}

// ---------------- classifier head ----------------
__global__ void classify(const float* __restrict__ w1, const float* __restrict__ b1,
                         const float* __restrict__ w2, const float* __restrict__ b2,
                         float* __restrict__ outv)
{
    int g = blockIdx.x;
    int j = threadIdx.x;
    float s = b1[j];
    for (int k = 0; k < 768; k++)
        s = fmaf(g_pooled[g * 768 + k], w1[k * 128 + j], s);
    s = fmaxf(s, 0.f);
    float t = s * w2[j];
    __shared__ float red[128];
    red[j] = t; __syncthreads();
    for (int o = 64; o; o >>= 1) { if (j < o) red[j] += red[j + o]; __syncthreads(); }
    if (!j) outv[g] = red[0] + b2[0];
}

// ---------------- launch ----------------
extern "C" void kernel_launch(void* const* d_in, const int* in_sizes, int n_in,
                              void* d_out, int out_size)
{
    const float* x        = (const float*)d_in[0];
    const int*   ei       = (const int*)d_in[1];
    const int*   batch    = (const int*)d_in[2];
    const float* proj_w   = (const float*)d_in[3];
    const float* proj_b   = (const float*)d_in[4];
    const float* gat1_w   = (const float*)d_in[5];
    const float* att1_src = (const float*)d_in[6];
    const float* att1_dst = (const float*)d_in[7];
    const float* gat1_b   = (const float*)d_in[8];
    const float* ln1_g    = (const float*)d_in[9];
    const float* ln1_b    = (const float*)d_in[10];
    const float* gat2_w   = (const float*)d_in[11];
    const float* att2_src = (const float*)d_in[12];
    const float* att2_dst = (const float*)d_in[13];
    const float* gat2_b   = (const float*)d_in[14];
    const float* ln2_g    = (const float*)d_in[15];
    const float* ln2_b    = (const float*)d_in[16];
    const float* gat3_w   = (const float*)d_in[17];
    const float* att3_src = (const float*)d_in[18];
    const float* att3_dst = (const float*)d_in[19];
    const float* gat3_b   = (const float*)d_in[20];
    const float* ln3_g    = (const float*)d_in[21];
    const float* ln3_b    = (const float*)d_in[22];
    const float* cls1_w   = (const float*)d_in[23];
    const float* cls1_b   = (const float*)d_in[24];
    const float* cls2_w   = (const float*)d_in[25];
    const float* cls2_b   = (const float*)d_in[26];

    const int N = in_sizes[0] / 768;
    const int E = in_sizes[1] / 2;
    const int G = out_size;

    float* bufA; cudaGetSymbolAddress((void**)&bufA, g_bufA);
    float* bufB; cudaGetSymbolAddress((void**)&bufB, g_bufB);
    float* bufC; cudaGetSymbolAddress((void**)&bufC, g_bufC);
    __nv_bfloat16 *h0, *l0, *h1, *l1;
    cudaGetSymbolAddress((void**)&h0, g_h0); cudaGetSymbolAddress((void**)&l0, g_l0);
    cudaGetSymbolAddress((void**)&h1, g_h1); cudaGetSymbolAddress((void**)&l1, g_l1);
    __nv_bfloat16 *wPh, *wPl, *w1h, *w1l, *w2h, *w2l, *w3h, *w3l;
    cudaGetSymbolAddress((void**)&wPh, g_wPh); cudaGetSymbolAddress((void**)&wPl, g_wPl);
    cudaGetSymbolAddress((void**)&w1h, g_w1h); cudaGetSymbolAddress((void**)&w1l, g_w1l);
    cudaGetSymbolAddress((void**)&w2h, g_w2h); cudaGetSymbolAddress((void**)&w2l, g_w2l);
    cudaGetSymbolAddress((void**)&w3h, g_w3h); cudaGetSymbolAddress((void**)&w3l, g_w3l);

    cudaFuncSetAttribute(mma_gemm<0>, cudaFuncAttributeMaxDynamicSharedMemorySize, GEMM_SMEM_TOTAL);
    cudaFuncSetAttribute(mma_gemm<1>, cudaFuncAttributeMaxDynamicSharedMemorySize, GEMM_SMEM_TOTAL);

    // CSR + graph segmentation
    zero_counts<<<(N + 255) / 256, 256>>>(N);
    count_deg<<<(E + 255) / 256, 256>>>(ei, E);
    count_graphs<<<(N + 255) / 256, 256>>>(batch, N);
    scan_deg<<<1, 1024>>>(N);
    graph_offsets<<<1, 32>>>();
    fill_csr<<<(E + 255) / 256, 256>>>(ei, E);

    // operand preparation: split x, transpose+split weights
    split_f32<<<(N * 768 + 255) / 256, 256>>>(x, h1, l1, N * 768);
    dim3 tb(32, 8);
    transpose_split<<<dim3(768 / 32, 768 / 32), tb>>>(proj_w, wPh, wPl, 768, 768);
    transpose_split<<<dim3(1024 / 32, 768 / 32), tb>>>(gat1_w, w1h, w1l, 768, 1024);
    transpose_split<<<dim3(1024 / 32, 1024 / 32), tb>>>(gat2_w, w2h, w2l, 1024, 1024);
    transpose_split<<<dim3(256 / 32, 1024 / 32), tb>>>(gat3_w, w3h, w3l, 1024, 256);

    const int MT = (N + 127) / 128;

    // proj: h = elu(x @ proj_w + b) -> hi/lo slot0 only (feeds gemm1)
    mma_gemm<1><<<dim3(768 / 128, MT), 256, GEMM_SMEM_TOTAL>>>(
        h1, l1, wPh, wPl, proj_b, nullptr, h0, l0, N, 768, 768);

    // ---- GAT layer 1 ----
    mma_gemm<0><<<dim3(1024 / 128, MT), 256, GEMM_SMEM_TOTAL>>>(
        h0, l0, w1h, w1l, nullptr, bufB, nullptr, nullptr, N, 1024, 768);
    att_scores<4><<<(N * 4 + 7) / 8, 256>>>(bufB, att1_src, att1_dst, N);
    gat_agg<4, false><<<N, 256>>>(bufB, gat1_b, ln1_g, ln1_b, nullptr, bufC, h1, l1);   // bufC = x1

    // ---- GAT layer 2 ----
    mma_gemm<0><<<dim3(1024 / 128, MT), 256, GEMM_SMEM_TOTAL>>>(
        h1, l1, w2h, w2l, nullptr, bufB, nullptr, nullptr, N, 1024, 1024);
    att_scores<4><<<(N * 4 + 7) / 8, 256>>>(bufB, att2_src, att2_dst, N);
    gat_agg<4, true><<<N, 256>>>(bufB, gat2_b, ln2_g, ln2_b, bufC, bufA, h0, l0);       // x2 -> slot0

    // ---- GAT layer 3 ----
    mma_gemm<0><<<dim3(256 / 128, MT), 256, GEMM_SMEM_TOTAL>>>(
        h0, l0, w3h, w3l, nullptr, bufB, nullptr, nullptr, N, 256, 1024);
    att_scores<1><<<(N + 7) / 8, 256>>>(bufB, att3_src, att3_dst, N);
    gat_agg<1, false><<<N, 64>>>(bufB, gat3_b, ln3_g, ln3_b, nullptr, bufC, nullptr, nullptr); // x3

    // ---- pooling + classifier ----
    pool_kernel<<<G, 256>>>(bufC);
    classify<<<G, 128>>>(cls1_w, cls1_b, cls2_w, cls2_b, (float*)d_out);
}

// round 16
// speedup vs baseline: 1.1157x; 1.0118x over previous
#include <cuda_runtime.h>
#include <cuda_bf16.h>
#include <math.h>
#include <stdint.h>

// ---------------- problem constants (fixed dataset) ----------------
#define MAX_N 20000
#define MAX_E 320000
#define NGRAPH 32

// ---------------- scratch (static device memory; no allocs) --------
__device__ float g_bufA[MAX_N * 1024];
__device__ float g_bufB[MAX_N * 1024];
__device__ float g_bufC[MAX_N * 1024];
__device__ float g_es[MAX_N * 4];
__device__ float g_ed[MAX_N * 4];
__device__ int   g_deg[MAX_N];
__device__ int   g_off[MAX_N + 1];
__device__ int   g_cur[MAX_N];
__device__ int   g_srcidx[MAX_E];
__device__ int   g_gcnt[NGRAPH];
__device__ int   g_goff[NGRAPH];
__device__ float g_pooled[NGRAPH * 768];
__device__ int   g_tilectr[8];
// bf16 hi/lo activation slots (double-rounded split), stride = feature dim
__device__ __nv_bfloat16 g_h0[MAX_N * 1024], g_l0[MAX_N * 1024];
__device__ __nv_bfloat16 g_h1[MAX_N * 1024], g_l1[MAX_N * 1024];
// bf16 hi/lo transposed weights, [N,K] K-major
__device__ __nv_bfloat16 g_wPh[768 * 768],   g_wPl[768 * 768];
__device__ __nv_bfloat16 g_w1h[1024 * 768],  g_w1l[1024 * 768];
__device__ __nv_bfloat16 g_w2h[1024 * 1024], g_w2l[1024 * 1024];
__device__ __nv_bfloat16 g_w3h[256 * 1024],  g_w3l[256 * 1024];

// ---------------- helpers ----------------
__device__ __forceinline__ float lrelu(float x) { return x > 0.f ? x : 0.2f * x; }
__device__ __forceinline__ float elu(float x)   { return x > 0.f ? x : expm1f(x); }

__device__ __forceinline__ void split_bf16(float x, __nv_bfloat16& h, __nv_bfloat16& l) {
    h = __float2bfloat16(x);
    l = __float2bfloat16(x - __bfloat162float(h));
}
__device__ __forceinline__ uint32_t smem_u32(const void* p) {
    uint32_t a;
    asm("{ .reg .u64 t; cvta.to.shared.u64 t, %1; cvt.u32.u64 %0, t; }" : "=r"(a) : "l"(p));
    return a;
}
__device__ __forceinline__ void cp_async16(uint32_t saddr, const void* gaddr, int srcsz) {
    asm volatile("cp.async.cg.shared.global [%0], [%1], 16, %2;"
                 :: "r"(saddr), "l"(gaddr), "r"(srcsz) : "memory");
}
__device__ __forceinline__ void mma_bf16(float* d, const uint32_t* a, const uint32_t* b) {
    asm volatile(
        "mma.sync.aligned.m16n8k16.row.col.f32.bf16.bf16.f32 "
        "{%0,%1,%2,%3}, {%4,%5,%6,%7}, {%8,%9}, {%0,%1,%2,%3};"
        : "+f"(d[0]), "+f"(d[1]), "+f"(d[2]), "+f"(d[3])
        : "r"(a[0]), "r"(a[1]), "r"(a[2]), "r"(a[3]), "r"(b[0]), "r"(b[1]));
}
__device__ __forceinline__ void ldm_x4(uint32_t* r, uint32_t addr) {
    asm volatile("ldmatrix.sync.aligned.m8n8.x4.shared.b16 {%0,%1,%2,%3}, [%4];"
                 : "=r"(r[0]), "=r"(r[1]), "=r"(r[2]), "=r"(r[3]) : "r"(addr));
}

// ---------------- bf16x3 mma.sync persistent GEMM: C[M,N] = A @ Bt^T --------
// D = Ahi*Bhi + Ahi*Blo + Alo*Bhi (fp32 acc) ~= fp32 GEMM, err ~2^-18.
// Persistent CTAs pull 128x128 tiles from an atomic counter (no wave
// quantization). BK=32, 2-stage cp.async double-buffer, 8 warps (2x4),
// warp tile 64x32, 2 CTAs/SM. HATT>0: fused attention-score epilogue
// (es/ed += row . a_src/a_dst) via quad-shuffle + global atomicAdd.
#define GEMM_BK 32
#define APAD 40                         // bf16 per row (32 data + 8 pad) = 80B
#define ROWB (APAD * 2)                 // 80 bytes
#define TILEB (128 * ROWB)              // 10240 bytes per (matrix x hi/lo) tile
#define STG_BYTES (4 * TILEB)           // Ahi, Alo, Bhi, Blo = 40960
#define GEMM_SMEM_TOTAL (2 * STG_BYTES)
#define GEMM_GRID 296                   // 2 CTAs x 148 SMs

template<int ACT, int HATT>   // ACT: 0 none, 1 ELU.  HATT: 0 off, else #heads
__global__ void __launch_bounds__(256, 2)
mma_gemm(const __nv_bfloat16* __restrict__ Ahi, const __nv_bfloat16* __restrict__ Alo,
         const __nv_bfloat16* __restrict__ Bhi, const __nv_bfloat16* __restrict__ Blo,
         const float* __restrict__ bias, float* __restrict__ C,
         __nv_bfloat16* __restrict__ Chi, __nv_bfloat16* __restrict__ Clo,
         const float* __restrict__ asrc, const float* __restrict__ adst,
         float* __restrict__ es, float* __restrict__ ed,
         int M, int N, int K, int ctrSlot)
{
    extern __shared__ char smem_raw[];
    __shared__ int s_tile;
    const int tid = threadIdx.x;
    const int lane = tid & 31;
    const int warp = tid >> 5;
    const int wm = warp & 1;         // 2 warps along M (64 rows each)
    const int wn = warp >> 1;        // 4 warps along N (32 cols each)
    const int qr = lane >> 2;        // 0..7
    const int qc = lane & 3;         // 0..3

    const uint32_t sbase = smem_u32(smem_raw);
    const int NC = K / GEMM_BK;
    const int NX = N >> 7;                    // N tiles
    const int MT = (M + 127) >> 7;
    const int nTiles = NX * MT;

    // ldmatrix per-lane offsets (verified mapping):
    const uint32_t aOff = (uint32_t)(wm * 64 + (lane & 15)) * ROWB + (lane >> 4) * 16;
    const uint32_t bOff = (uint32_t)(wn * 32 + ((lane >> 4) << 3) + (lane & 7)) * ROWB
                          + ((lane >> 3) & 1) * 16;

    while (true) {
        if (tid == 0) s_tile = atomicAdd(&g_tilectr[ctrSlot], 1);
        __syncthreads();
        const int t = s_tile;
        __syncthreads();                 // s_tile consumed before next overwrite
        if (t >= nTiles) break;
        const int row0 = (t / NX) * 128;
        const int col0 = (t % NX) * 128;

        float acc[4][4][4];
#pragma unroll
        for (int i = 0; i < 4; i++)
#pragma unroll
            for (int j = 0; j < 4; j++)
#pragma unroll
                for (int r = 0; r < 4; r++) acc[i][j][r] = 0.f;

        auto load_tile = [&](int c, int s) {
            const int k0 = c * GEMM_BK;
            const uint32_t stb = sbase + s * STG_BYTES;
#pragma unroll
            for (int tt = 0; tt < 8; tt++) {
                int id = tt * 256 + tid;
                int tile = id >> 9;          // 0 Ahi, 1 Alo, 2 Bhi, 3 Blo
                int wi = id & 511;
                int r = wi >> 2, q = wi & 3;
                uint32_t soff = stb + tile * TILEB + r * ROWB + q * 16;
                const __nv_bfloat16* g;
                int sz = 16;
                if (tile == 0)      { g = Ahi + (size_t)(row0 + r) * K + k0 + q * 8; if (row0 + r >= M) sz = 0; }
                else if (tile == 1) { g = Alo + (size_t)(row0 + r) * K + k0 + q * 8; if (row0 + r >= M) sz = 0; }
                else if (tile == 2) { g = Bhi + (size_t)(col0 + r) * K + k0 + q * 8; }
                else                { g = Blo + (size_t)(col0 + r) * K + k0 + q * 8; }
                cp_async16(soff, g, sz);
            }
            asm volatile("cp.async.commit_group;" ::: "memory");
        };

        load_tile(0, 0);
        load_tile(1, 1);

        for (int c = 0; c < NC; c++) {
            const int s = c & 1;
            if (c < NC - 1) asm volatile("cp.async.wait_group 1;" ::: "memory");
            else            asm volatile("cp.async.wait_group 0;" ::: "memory");
            __syncthreads();

            const uint32_t stb = sbase + s * STG_BYTES;
#pragma unroll
            for (int ks = 0; ks < 2; ks++) {
                const uint32_t kb = ks * 32;
                uint32_t ah[4][4], al[4][4], bh[4][2], bl[4][2];
#pragma unroll
                for (int i = 0; i < 4; i++) {
                    ldm_x4(ah[i], stb + 0 * TILEB + aOff + i * (16 * ROWB) + kb);
                    ldm_x4(al[i], stb + 1 * TILEB + aOff + i * (16 * ROWB) + kb);
                }
#pragma unroll
                for (int j2 = 0; j2 < 2; j2++) {
                    uint32_t rh[4], rl[4];
                    ldm_x4(rh, stb + 2 * TILEB + bOff + j2 * (16 * ROWB) + kb);
                    ldm_x4(rl, stb + 3 * TILEB + bOff + j2 * (16 * ROWB) + kb);
                    bh[2 * j2][0] = rh[0]; bh[2 * j2][1] = rh[1];
                    bh[2 * j2 + 1][0] = rh[2]; bh[2 * j2 + 1][1] = rh[3];
                    bl[2 * j2][0] = rl[0]; bl[2 * j2][1] = rl[1];
                    bl[2 * j2 + 1][0] = rl[2]; bl[2 * j2 + 1][1] = rl[3];
                }
#pragma unroll
                for (int i = 0; i < 4; i++)
#pragma unroll
                    for (int j = 0; j < 4; j++) {
                        mma_bf16(acc[i][j], ah[i], bh[j]);
                        mma_bf16(acc[i][j], ah[i], bl[j]);
                        mma_bf16(acc[i][j], al[i], bh[j]);
                    }
            }
            __syncthreads();
            if (c + 2 < NC) load_tile(c + 2, s);
        }

        // ---- epilogue ----
        float asv[4][2], adv[4][2];
        if (HATT > 0) {
            const int h = col0 >> 8;
#pragma unroll
            for (int j = 0; j < 4; j++) {
                int cm = (col0 + wn * 32 + j * 8 + 2 * qc) & 255;
                asv[j][0] = asrc[h * 256 + cm];     asv[j][1] = asrc[h * 256 + cm + 1];
                adv[j][0] = adst[h * 256 + cm];     adv[j][1] = adst[h * 256 + cm + 1];
            }
        }
        float ps[8], pd[8];
#pragma unroll
        for (int r = 0; r < 8; r++) { ps[r] = 0.f; pd[r] = 0.f; }

#pragma unroll
        for (int i = 0; i < 4; i++) {
#pragma unroll
            for (int j = 0; j < 4; j++) {
                const int cc = col0 + wn * 32 + j * 8 + 2 * qc;
                float b0 = 0.f, b1 = 0.f;
                if (bias) { b0 = bias[cc]; b1 = bias[cc + 1]; }
#pragma unroll
                for (int half = 0; half < 2; half++) {
                    int r = row0 + wm * 64 + i * 16 + qr + half * 8;
                    if (r >= M) continue;
                    float v0 = acc[i][j][half * 2 + 0] + b0;
                    float v1 = acc[i][j][half * 2 + 1] + b1;
                    if (ACT == 1) { v0 = elu(v0); v1 = elu(v1); }
                    if (HATT > 0) {
                        ps[i * 2 + half] += v0 * asv[j][0] + v1 * asv[j][1];
                        pd[i * 2 + half] += v0 * adv[j][0] + v1 * adv[j][1];
                    }
                    if (C) *(float2*)&C[(size_t)r * N + cc] = make_float2(v0, v1);
                    if (Chi) {
                        __nv_bfloat16 h0, l0, h1, l1;
                        split_bf16(v0, h0, l0);
                        split_bf16(v1, h1, l1);
                        __nv_bfloat162 hp; hp.x = h0; hp.y = h1;
                        __nv_bfloat162 lp; lp.x = l0; lp.y = l1;
                        *(__nv_bfloat162*)&Chi[(size_t)r * N + cc] = hp;
                        *(__nv_bfloat162*)&Clo[(size_t)r * N + cc] = lp;
                    }
                }
            }
        }
        if (HATT > 0) {
            const int h = col0 >> 8;
#pragma unroll
            for (int r = 0; r < 8; r++) {
#pragma unroll
                for (int off = 1; off <= 2; off <<= 1) {
                    ps[r] += __shfl_xor_sync(0xFFFFFFFFu, ps[r], off);
                    pd[r] += __shfl_xor_sync(0xFFFFFFFFu, pd[r], off);
                }
            }
            if (qc == 0) {
#pragma unroll
                for (int i = 0; i < 4; i++)
#pragma unroll
                    for (int half = 0; half < 2; half++) {
                        int r = row0 + wm * 64 + i * 16 + qr + half * 8;
                        if (r < M) {
                            atomicAdd(&es[r * HATT + h], ps[i * 2 + half]);
                            atomicAdd(&ed[r * HATT + h], pd[i * 2 + half]);
                        }
                    }
            }
        }
    }
}

// ---------------- split fp32 -> bf16 hi/lo (also resets tile counters) ------
__global__ void split_f32(const float* __restrict__ in,
                          __nv_bfloat16* __restrict__ hi, __nv_bfloat16* __restrict__ lo, int n)
{
    int i = blockIdx.x * blockDim.x + threadIdx.x;
    if (blockIdx.x == 0 && threadIdx.x < 8) g_tilectr[threadIdx.x] = 0;
    if (i < n) {
        __nv_bfloat16 h, l;
        split_bf16(in[i], h, l);
        hi[i] = h; lo[i] = l;
    }
}

// ---------------- weight transpose + split ----------------
__global__ void transpose_split(const float* __restrict__ in,
                                __nv_bfloat16* __restrict__ oh, __nv_bfloat16* __restrict__ ol,
                                int K, int N)
{
    __shared__ float t[32][33];
    const int n0 = blockIdx.x * 32, k0 = blockIdx.y * 32;
    const int tx = threadIdx.x, ty = threadIdx.y;   // 32 x 8
#pragma unroll
    for (int i = 0; i < 32; i += 8)
        t[ty + i][tx] = in[(size_t)(k0 + ty + i) * N + n0 + tx];
    __syncthreads();
#pragma unroll
    for (int i = 0; i < 32; i += 8) {
        float v = t[tx][ty + i];
        __nv_bfloat16 h, l;
        split_bf16(v, h, l);
        oh[(size_t)(n0 + ty + i) * K + k0 + tx] = h;
        ol[(size_t)(n0 + ty + i) * K + k0 + tx] = l;
    }
}

// ---------------- CSR construction ----------------
__global__ void zero_counts(int n) {      // also zeros es/ed for layer 1 (H=4)
    int i = blockIdx.x * blockDim.x + threadIdx.x;
    if (i < n) {
        g_deg[i] = 0;
#pragma unroll
        for (int h = 0; h < 4; h++) { g_es[i * 4 + h] = 0.f; g_ed[i * 4 + h] = 0.f; }
    }
    if (i < NGRAPH) g_gcnt[i] = 0;
}
__global__ void zero_esed(int cnt) {
    int i = blockIdx.x * blockDim.x + threadIdx.x;
    if (i < cnt) { g_es[i] = 0.f; g_ed[i] = 0.f; }
}
__global__ void count_deg(const int* __restrict__ ei, int E) {
    int i = blockIdx.x * blockDim.x + threadIdx.x;
    if (i < E) atomicAdd(&g_deg[ei[E + i]], 1);
}
__global__ void count_graphs(const int* __restrict__ batch, int n) {
    int i = blockIdx.x * blockDim.x + threadIdx.x;
    if (i < n) atomicAdd(&g_gcnt[batch[i]], 1);
}
__global__ void scan_deg(int n) {         // warp-shuffle two-level scan
    __shared__ int wsum[32];
    const int tid = threadIdx.x, lane = tid & 31, wid = tid >> 5;
    const int per = (n + 1023) >> 10;
    const int base = tid * per;
    int s = 0;
    for (int k = 0; k < per; k++) { int idx = base + k; if (idx < n) s += g_deg[idx]; }
    int sc = s;
#pragma unroll
    for (int off = 1; off < 32; off <<= 1) {
        int v = __shfl_up_sync(0xFFFFFFFFu, sc, off);
        if (lane >= off) sc += v;
    }
    if (lane == 31) wsum[wid] = sc;
    __syncthreads();
    if (wid == 0) {
        int w = wsum[lane];
#pragma unroll
        for (int off = 1; off < 32; off <<= 1) {
            int v = __shfl_up_sync(0xFFFFFFFFu, w, off);
            if (lane >= off) w += v;
        }
        wsum[lane] = w;
    }
    __syncthreads();
    int run = sc - s + (wid ? wsum[wid - 1] : 0);
    for (int k = 0; k < per; k++) {
        int idx = base + k;
        if (idx < n) { g_off[idx] = run; g_cur[idx] = run; run += g_deg[idx]; }
    }
    if (tid == 1023) g_off[n] = wsum[31];
}
__global__ void graph_offsets() {
    if (threadIdx.x == 0) {
        int r = 0;
        for (int g = 0; g < NGRAPH; g++) { g_goff[g] = r; r += g_gcnt[g]; }
    }
}
__global__ void fill_csr(const int* __restrict__ ei, int E) {
    int i = blockIdx.x * blockDim.x + threadIdx.x;
    if (i < E) {
        int d = ei[E + i];
        int p = atomicAdd(&g_cur[d], 1);
        g_srcidx[p] = ei[i];
    }
}

// ---------------- fused GAT aggregation + bias + LayerNorm + ELU (+residual) ----
template<int H, bool RES>
__global__ void gat_agg(const float* __restrict__ hW,
                        const float* __restrict__ bias,
                        const float* __restrict__ lng,
                        const float* __restrict__ lnb,
                        const float* __restrict__ resid,
                        float* __restrict__ out,
                        __nv_bfloat16* __restrict__ ohi,
                        __nv_bfloat16* __restrict__ olo)
{
    constexpr int CT = H * 256;
    constexpr int NT = CT / 4;
    constexpr int NW = NT / 32;
    constexpr int CHUNK = 64;

    __shared__ float2 wred[NW][H];
    __shared__ float  alpha_sm[CHUNK * H];
    __shared__ int    sidx_sm[CHUNK];
    __shared__ float  lnr[NW][2];

    const int i = blockIdx.x;
    const int tid = threadIdx.x;
    const int lane = tid & 31, wid = tid >> 5;
    const int c0 = tid * 4;
    const int head = c0 >> 8;
    const int start = g_off[i], end = g_off[i + 1];

    float edv[H], selfl[H];
#pragma unroll
    for (int h = 0; h < H; h++) {
        edv[h] = g_ed[i * H + h];
        selfl[h] = lrelu(g_es[i * H + h] + edv[h]);
    }

    float m[H], s[H];
#pragma unroll
    for (int h = 0; h < H; h++) { m[h] = -1e30f; s[h] = 0.f; }
    for (int e = start + tid; e < end; e += NT) {
        int sd = g_srcidx[e];
#pragma unroll
        for (int h = 0; h < H; h++) {
            float l = lrelu(g_es[sd * H + h] + edv[h]);
            if (l > m[h]) { s[h] = s[h] * __expf(m[h] - l) + 1.f; m[h] = l; }
            else          { s[h] += __expf(l - m[h]); }
        }
    }
#pragma unroll
    for (int off = 16; off; off >>= 1) {
#pragma unroll
        for (int h = 0; h < H; h++) {
            float m2 = __shfl_xor_sync(0xFFFFFFFFu, m[h], off);
            float s2 = __shfl_xor_sync(0xFFFFFFFFu, s[h], off);
            if (m2 > m[h]) { s[h] = s[h] * __expf(m[h] - m2) + s2; m[h] = m2; }
            else           { s[h] += s2 * __expf(m2 - m[h]); }
        }
    }
    if (lane == 0) {
#pragma unroll
        for (int h = 0; h < H; h++) wred[wid][h] = make_float2(m[h], s[h]);
    }
    __syncthreads();

    float M[H], inv[H];
#pragma unroll
    for (int h = 0; h < H; h++) {
        float Mv = -1e30f, Sv = 0.f;
#pragma unroll
        for (int w = 0; w < NW; w++) {
            float2 p = wred[w][h];
            if (p.x > Mv) { Sv = Sv * __expf(Mv - p.x) + p.y; Mv = p.x; }
            else          { Sv += p.y * __expf(p.x - Mv); }
        }
        if (selfl[h] > Mv) { Sv = Sv * __expf(Mv - selfl[h]) + 1.f; Mv = selfl[h]; }
        else               { Sv += __expf(selfl[h] - Mv); }
        M[h] = Mv; inv[h] = 1.f / (Sv + 1e-16f);
    }

    float4 acc;
    {
        float a = __expf(selfl[head] - M[head]) * inv[head];
        float4 v = *(const float4*)&hW[(size_t)i * CT + c0];
        acc = make_float4(a * v.x, a * v.y, a * v.z, a * v.w);
    }
    for (int base = start; base < end; base += CHUNK) {
        int nE = min(CHUNK, end - base);
        __syncthreads();
        int e2, hh;
        if (H == 4) { e2 = tid >> 2; hh = tid & 3; }
        else        { e2 = tid;      hh = 0; }
        if (e2 < nE) {
            int sd = g_srcidx[base + e2];
            if (hh == 0) sidx_sm[e2] = sd;
            float l = lrelu(g_es[sd * H + hh] + edv[hh]);
            alpha_sm[e2 * H + hh] = __expf(l - M[hh]) * inv[hh];
        }
        __syncthreads();
        for (int k = 0; k < nE; k++) {
            int sd = sidx_sm[k];
            float a = alpha_sm[k * H + head];
            float4 v = *(const float4*)&hW[(size_t)sd * CT + c0];
            acc.x = fmaf(a, v.x, acc.x);
            acc.y = fmaf(a, v.y, acc.y);
            acc.z = fmaf(a, v.z, acc.z);
            acc.w = fmaf(a, v.w, acc.w);
        }
    }
    {
        float4 b = *(const float4*)&bias[c0];
        acc.x += b.x; acc.y += b.y; acc.z += b.z; acc.w += b.w;
    }

    float s1 = acc.x + acc.y + acc.z + acc.w;
    float s2 = acc.x * acc.x + acc.y * acc.y + acc.z * acc.z + acc.w * acc.w;
#pragma unroll
    for (int off = 16; off; off >>= 1) {
        s1 += __shfl_xor_sync(0xFFFFFFFFu, s1, off);
        s2 += __shfl_xor_sync(0xFFFFFFFFu, s2, off);
    }
    if (lane == 0) { lnr[wid][0] = s1; lnr[wid][1] = s2; }
    __syncthreads();
    float S1 = 0.f, S2 = 0.f;
#pragma unroll
    for (int w = 0; w < NW; w++) { S1 += lnr[w][0]; S2 += lnr[w][1]; }

    float mu = S1 / (float)CT;
    float var = S2 / (float)CT - mu * mu;
    float rstd = rsqrtf(var + 1e-5f);
    float4 gv = *(const float4*)&lng[c0];
    float4 bv = *(const float4*)&lnb[c0];
    float o0 = elu((acc.x - mu) * rstd * gv.x + bv.x);
    float o1 = elu((acc.y - mu) * rstd * gv.y + bv.y);
    float o2 = elu((acc.z - mu) * rstd * gv.z + bv.z);
    float o3 = elu((acc.w - mu) * rstd * gv.w + bv.w);
    if (RES) {
        float4 rv = *(const float4*)&resid[(size_t)i * CT + c0];
        o0 += rv.x; o1 += rv.y; o2 += rv.z; o3 += rv.w;
    }
    *(float4*)&out[(size_t)i * CT + c0] = make_float4(o0, o1, o2, o3);

    if (ohi) {
        __nv_bfloat16 h[4], l[4];
        split_bf16(o0, h[0], l[0]);
        split_bf16(o1, h[1], l[1]);
        split_bf16(o2, h[2], l[2]);
        split_bf16(o3, h[3], l[3]);
        __nv_bfloat162 hp0; hp0.x = h[0]; hp0.y = h[1];
        __nv_bfloat162 hp1; hp1.x = h[2]; hp1.y = h[3];
        __nv_bfloat162 lp0; lp0.x = l[0]; lp0.y = l[1];
        __nv_bfloat162 lp1; lp1.x = l[2]; lp1.y = l[3];
        *(__nv_bfloat162*)&ohi[(size_t)i * CT + c0] = hp0;
        *(__nv_bfloat162*)&ohi[(size_t)i * CT + c0 + 2] = hp1;
        *(__nv_bfloat162*)&olo[(size_t)i * CT + c0] = lp0;
        *(__nv_bfloat162*)&olo[(size_t)i * CT + c0 + 2] = lp1;
    }
}

// ---------------- per-graph pooling: mean | max | sum ----------------
__global__ void pool_kernel(const float* __restrict__ x3) {
    int g = blockIdx.x;
    int tid = threadIdx.x;
    int s = g_goff[g], cnt = g_gcnt[g];
    float sum = 0.f, mx = -INFINITY;
    for (int k = 0; k < cnt; k++) {
        float v = x3[(size_t)(s + k) * 256 + tid];
        sum += v;
        mx = fmaxf(mx, v);
    }
    float mean = sum / fmaxf((float)cnt, 1.f);
    g_pooled[g * 768 + tid] = mean;
    g_pooled[g * 768 + 256 + tid] = mx;
    g_pooled[g * 768 + 512 + tid] = sum;
}

// ---------------- classifier head ----------------
__global__ void classify(const float* __restrict__ w1, const float* __restrict__ b1,
                         const float* __restrict__ w2, const float* __restrict__ b2,
                         float* __restrict__ outv)
{
    int g = blockIdx.x;
    int j = threadIdx.x;
    float s = b1[j];
    for (int k = 0; k < 768; k++)
        s = fmaf(g_pooled[g * 768 + k], w1[k * 128 + j], s);
    s = fmaxf(s, 0.f);
    float t = s * w2[j];
    __shared__ float red[128];
    red[j] = t; __syncthreads();
    for (int o = 64; o; o >>= 1) { if (j < o) red[j] += red[j + o]; __syncthreads(); }
    if (!j) outv[g] = red[0] + b2[0];
}

// ---------------- launch ----------------
extern "C" void kernel_launch(void* const* d_in, const int* in_sizes, int n_in,
                              void* d_out, int out_size)
{
    const float* x        = (const float*)d_in[0];
    const int*   ei       = (const int*)d_in[1];
    const int*   batch    = (const int*)d_in[2];
    const float* proj_w   = (const float*)d_in[3];
    const float* proj_b   = (const float*)d_in[4];
    const float* gat1_w   = (const float*)d_in[5];
    const float* att1_src = (const float*)d_in[6];
    const float* att1_dst = (const float*)d_in[7];
    const float* gat1_b   = (const float*)d_in[8];
    const float* ln1_g    = (const float*)d_in[9];
    const float* ln1_b    = (const float*)d_in[10];
    const float* gat2_w   = (const float*)d_in[11];
    const float* att2_src = (const float*)d_in[12];
    const float* att2_dst = (const float*)d_in[13];
    const float* gat2_b   = (const float*)d_in[14];
    const float* ln2_g    = (const float*)d_in[15];
    const float* ln2_b    = (const float*)d_in[16];
    const float* gat3_w   = (const float*)d_in[17];
    const float* att3_src = (const float*)d_in[18];
    const float* att3_dst = (const float*)d_in[19];
    const float* gat3_b   = (const float*)d_in[20];
    const float* ln3_g    = (const float*)d_in[21];
    const float* ln3_b    = (const float*)d_in[22];
    const float* cls1_w   = (const float*)d_in[23];
    const float* cls1_b   = (const float*)d_in[24];
    const float* cls2_w   = (const float*)d_in[25];
    const float* cls2_b   = (const float*)d_in[26];

    const int N = in_sizes[0] / 768;
    const int E = in_sizes[1] / 2;
    const int G = out_size;

    float* bufA; cudaGetSymbolAddress((void**)&bufA, g_bufA);
    float* bufB; cudaGetSymbolAddress((void**)&bufB, g_bufB);
    float* bufC; cudaGetSymbolAddress((void**)&bufC, g_bufC);
    float* esp;  cudaGetSymbolAddress((void**)&esp, g_es);
    float* edp;  cudaGetSymbolAddress((void**)&edp, g_ed);
    __nv_bfloat16 *h0, *l0, *h1, *l1;
    cudaGetSymbolAddress((void**)&h0, g_h0); cudaGetSymbolAddress((void**)&l0, g_l0);
    cudaGetSymbolAddress((void**)&h1, g_h1); cudaGetSymbolAddress((void**)&l1, g_l1);
    __nv_bfloat16 *wPh, *wPl, *w1h, *w1l, *w2h, *w2l, *w3h, *w3l;
    cudaGetSymbolAddress((void**)&wPh, g_wPh); cudaGetSymbolAddress((void**)&wPl, g_wPl);
    cudaGetSymbolAddress((void**)&w1h, g_w1h); cudaGetSymbolAddress((void**)&w1l, g_w1l);
    cudaGetSymbolAddress((void**)&w2h, g_w2h); cudaGetSymbolAddress((void**)&w2l, g_w2l);
    cudaGetSymbolAddress((void**)&w3h, g_w3h); cudaGetSymbolAddress((void**)&w3l, g_w3l);

    cudaFuncSetAttribute(mma_gemm<1, 0>, cudaFuncAttributeMaxDynamicSharedMemorySize, GEMM_SMEM_TOTAL);
    cudaFuncSetAttribute(mma_gemm<0, 4>, cudaFuncAttributeMaxDynamicSharedMemorySize, GEMM_SMEM_TOTAL);
    cudaFuncSetAttribute(mma_gemm<0, 1>, cudaFuncAttributeMaxDynamicSharedMemorySize, GEMM_SMEM_TOTAL);

    // ---- prep (order chosen so launch #6 = proj GEMM for ncu capture) ----
    split_f32<<<(N * 768 + 255) / 256, 256>>>(x, h1, l1, N * 768);        // 1 (+ctr reset)
    dim3 tb(32, 8);
    transpose_split<<<dim3(768 / 32, 768 / 32), tb>>>(proj_w, wPh, wPl, 768, 768);     // 2
    transpose_split<<<dim3(1024 / 32, 768 / 32), tb>>>(gat1_w, w1h, w1l, 768, 1024);   // 3
    transpose_split<<<dim3(1024 / 32, 1024 / 32), tb>>>(gat2_w, w2h, w2l, 1024, 1024); // 4
    transpose_split<<<dim3(256 / 32, 1024 / 32), tb>>>(gat3_w, w3h, w3l, 1024, 256);   // 5

    // 6: proj GEMM  h = elu(x @ proj_w + b) -> hi/lo slot0
    mma_gemm<1, 0><<<GEMM_GRID, 256, GEMM_SMEM_TOTAL>>>(
        h1, l1, wPh, wPl, proj_b, nullptr, h0, l0,
        nullptr, nullptr, nullptr, nullptr, N, 768, 768, 0);

    // CSR + graph segmentation (also zeros es/ed for layer 1)
    zero_counts<<<(N + 255) / 256, 256>>>(N);
    count_deg<<<(E + 255) / 256, 256>>>(ei, E);
    count_graphs<<<(N + 255) / 256, 256>>>(batch, N);
    scan_deg<<<1, 1024>>>(N);
    graph_offsets<<<1, 32>>>();
    fill_csr<<<(E + 255) / 256, 256>>>(ei, E);

    // ---- GAT layer 1 ----
    mma_gemm<0, 4><<<GEMM_GRID, 256, GEMM_SMEM_TOTAL>>>(
        h0, l0, w1h, w1l, nullptr, bufB, nullptr, nullptr,
        att1_src, att1_dst, esp, edp, N, 1024, 768, 1);
    gat_agg<4, false><<<N, 256>>>(bufB, gat1_b, ln1_g, ln1_b, nullptr, bufC, h1, l1);   // bufC = x1

    // ---- GAT layer 2 ----
    zero_esed<<<(N * 4 + 255) / 256, 256>>>(N * 4);
    mma_gemm<0, 4><<<GEMM_GRID, 256, GEMM_SMEM_TOTAL>>>(
        h1, l1, w2h, w2l, nullptr, bufB, nullptr, nullptr,
        att2_src, att2_dst, esp, edp, N, 1024, 1024, 2);
    gat_agg<4, true><<<N, 256>>>(bufB, gat2_b, ln2_g, ln2_b, bufC, bufA, h0, l0);       // x2 -> slot0

    // ---- GAT layer 3 ----
    zero_esed<<<(N + 255) / 256, 256>>>(N);
    mma_gemm<0, 1><<<GEMM_GRID, 256, GEMM_SMEM_TOTAL>>>(
        h0, l0, w3h, w3l, nullptr, bufB, nullptr, nullptr,
        att3_src, att3_dst, esp, edp, N, 256, 1024, 3);
    gat_agg<1, false><<<N, 64>>>(bufB, gat3_b, ln3_g, ln3_b, nullptr, bufC, nullptr, nullptr); // x3

    // ---- pooling + classifier ----
    pool_kernel<<<G, 256>>>(bufC);
    classify<<<G, 128>>>(cls1_w, cls1_b, cls2_w, cls2_b, (float*)d_out);
}